// round 8
// baseline (speedup 1.0000x reference)
#include <cuda_runtime.h>
#include <math.h>
#include <stdint.h>

#define BB 32
#define SS 4096
#define II 512
#define HH 512
#define NCH 16
#define CHUNK (SS / NCH)      // 256 positions per block
#define TILE 8                // positions per shared tile
#define NTILES (CHUNK / TILE) // 32
#define NBUF 3
#define NTHREADS 256
#define NEG_INF_F (-1e18f)
#define HSPLIT 8

// -------- persistent device scratch (no allocations allowed) --------
__device__ float g_part[2 * HSPLIT * II];  // [mat][hs][i] partials
__device__ float g_w2[II];                 // Wk^T @ Wout
__device__ float g_qoff[BB];               // per-batch additive score offset
__device__ float g_pm[BB * NCH];           // partial max
__device__ float g_pl[BB * NCH];           // partial sumexp
__device__ float g_pkbar[BB * NCH * II];   // partial weighted key sums
__device__ float g_kbar[BB * II];          // combined softmax-weighted key mean
__device__ int   g_cnt_prep;               // prep completion counter (init 0)
__device__ int   g_cnt[BB];                // per-batch main_pass counters (init 0)

// -------- cp.async helpers --------
__device__ __forceinline__ void cp_async16(void* dst_smem, const void* src_gmem) {
    unsigned d = (unsigned)__cvta_generic_to_shared(dst_smem);
    asm volatile("cp.async.cg.shared.global [%0], [%1], 16;\n" :: "r"(d), "l"(src_gmem));
}
__device__ __forceinline__ void cp_async_commit() {
    asm volatile("cp.async.commit_group;\n");
}
__device__ __forceinline__ void cp_async_wait1() {
    asm volatile("cp.async.wait_group 1;\n");
}
__device__ __forceinline__ void cp_async_wait0() {
    asm volatile("cp.async.wait_group 0;\n");
}

// ============================================================
// Kernel A: fused prep. 256 blocks compute h-split partials of
// Wk^T@Wout and Wq^T@Wout; the LAST block to finish combines
// them and computes g_w2, cbias, and all 32 qoff values.
// ============================================================
__global__ void __launch_bounds__(256) prep_fused(
    const float* __restrict__ query,
    const float* __restrict__ Wk, const float* __restrict__ Wq,
    const float* __restrict__ bq, const float* __restrict__ bk,
    const float* __restrict__ Wout)
{
    const int blk = blockIdx.x;
    const int mat = blk >> 7;
    const int rem = blk & 127;
    const int hs  = rem >> 4;
    const int ig  = rem & 15;
    const int i0  = ig * 32;
    const int h0  = hs * 64;
    const int tid = threadIdx.x;
    const int lane = tid & 31;
    const int warp = tid >> 5;

    const float* W = mat ? Wq : Wk;

    __shared__ float wout_sh[64];
    __shared__ float red[256];
    if (tid < 64) wout_sh[tid] = Wout[h0 + tid];
    __syncthreads();

    {
        const int il   = tid & 31;
        const int hsub = tid >> 5;
        float acc = 0.f;
        #pragma unroll
        for (int k = 0; k < 8; k++) {
            int hl = hsub * 8 + k;
            acc += W[(size_t)(h0 + hl) * II + i0 + il] * wout_sh[hl];
        }
        red[tid] = acc;
    }
    __syncthreads();
    if (tid < 128) red[tid] += red[tid + 128];
    __syncthreads();
    if (tid < 64) red[tid] += red[tid + 64];
    __syncthreads();
    if (tid < 32)
        g_part[(mat * HSPLIT + hs) * II + i0 + tid] = red[tid] + red[tid + 32];

    // ---- last-block combine ----
    __shared__ int lastflag;
    __threadfence();
    __syncthreads();
    if (tid == 0) {
        int v = atomicAdd(&g_cnt_prep, 1);
        lastflag = (v == gridDim.x - 1);
    }
    __syncthreads();
    if (!lastflag) return;
    __threadfence();

    __shared__ float wq2_sh[II];
    __shared__ float cred[256];
    __shared__ float cbias_sh;

    // g_w2 and wq2 (each thread: 2 i-values)
    #pragma unroll
    for (int j = 0; j < 2; j++) {
        int i = tid + j * 256;
        float sw = 0.f, sq = 0.f;
        #pragma unroll
        for (int h2 = 0; h2 < HSPLIT; h2++) {
            sw += g_part[h2 * II + i];
            sq += g_part[(HSPLIT + h2) * II + i];
        }
        g_w2[i] = sw;
        wq2_sh[i] = sq;
    }

    // cbias = Wout . (bq + bk)
    cred[tid] = Wout[tid] * (bq[tid] + bk[tid])
              + Wout[tid + 256] * (bq[tid + 256] + bk[tid + 256]);
    __syncthreads();
    for (int off = 128; off > 0; off >>= 1) {
        if (tid < off) cred[tid] += cred[tid + off];
        __syncthreads();
    }
    if (tid == 0) cbias_sh = cred[0];
    __syncthreads();

    // qoff: 8 warps x 4 batches each
    const float cbias = cbias_sh;
    #pragma unroll
    for (int j = 0; j < 4; j++) {
        int b = warp * 4 + j;
        const float* qrow = query + (size_t)b * II;
        float s = 0.f;
        #pragma unroll
        for (int k = 0; k < 16; k++)
            s += qrow[lane + 32 * k] * wq2_sh[lane + 32 * k];
        #pragma unroll
        for (int off = 16; off > 0; off >>= 1)
            s += __shfl_down_sync(0xffffffffu, s, off);
        if (lane == 0) g_qoff[b] = s + cbias;
    }

    if (tid == 0) g_cnt_prep = 0;   // reset for graph replay
}

// ============================================================
// Kernel B: streaming pass (unchanged core). The LAST block of
// each batch additionally combines that batch's partials into
// g_kbar (fused former combine_kbar).
// ============================================================
__global__ void __launch_bounds__(NTHREADS) main_pass(
    const float* __restrict__ key,
    const int* __restrict__ mask,
    float* __restrict__ out)
{
    const int b = blockIdx.x / NCH;
    const int c = blockIdx.x % NCH;
    const int tid = threadIdx.x;
    const int lane = tid & 31;
    const int warp = tid >> 5;
    const int s0 = c * CHUNK;
    const float* keyb = key + (size_t)b * SS * II + (size_t)s0 * II;

    extern __shared__ float smem[];
    float* bufs = smem;                          // NBUF * TILE*II floats
    float* sc_sh = smem + NBUF * TILE * II;      // TILE scores
    int*   mask_sh = (int*)(sc_sh + TILE);       // CHUNK ints

    mask_sh[tid] = mask[(size_t)b * SS + s0 + tid];

    float w2r[16];
    #pragma unroll
    for (int k = 0; k < 16; k++) w2r[k] = g_w2[lane + 32 * k];

    const float qoff = g_qoff[b];

    float kbar0 = 0.f, kbar1 = 0.f;
    float l = 0.f;
    float m_run = -3.0e38f;

    // preload tiles 0 and 1
    #pragma unroll
    for (int pt = 0; pt < 2; pt++) {
        const float* src = keyb + (size_t)pt * TILE * II;
        float* dst = bufs + pt * TILE * II;
        #pragma unroll
        for (int j = 0; j < 4; j++) {
            int idx = tid + j * NTHREADS;
            cp_async16(dst + idx * 4, src + idx * 4);
        }
        cp_async_commit();
    }

    for (int t = 0; t < NTILES; t++) {
        float* cur = bufs + (t % NBUF) * TILE * II;
        if (t + 1 < NTILES) cp_async_wait1();
        else cp_async_wait0();
        __syncthreads();

        // ---- scores: warp w handles position w (TILE==8) ----
        {
            const float* kr = cur + warp * II;
            float acc = 0.f;
            #pragma unroll
            for (int k = 0; k < 16; k++)
                acc += kr[lane + 32 * k] * w2r[k];
            #pragma unroll
            for (int off = 16; off > 0; off >>= 1)
                acc += __shfl_down_sync(0xffffffffu, acc, off);
            if (lane == 0) {
                float sc = acc + qoff;
                if (mask_sh[t * TILE + warp] != 0) sc = NEG_INF_F;
                sc_sh[warp] = sc;
            }
        }
        __syncthreads();

        if (tid < TILE)
            out[(size_t)BB * HH + (size_t)b * SS + s0 + t * TILE + tid] = sc_sh[tid];

        // ---- online softmax update ----
        float mt = -3.0e38f;
        #pragma unroll
        for (int tt = 0; tt < TILE; tt++) mt = fmaxf(mt, sc_sh[tt]);
        float m_new = fmaxf(m_run, mt);
        float scale = __expf(m_run - m_new);

        float pr[TILE];
        #pragma unroll
        for (int tt = 0; tt < TILE; tt++) pr[tt] = __expf(sc_sh[tt] - m_new);

        kbar0 *= scale;
        kbar1 *= scale;
        float tsum = 0.f;
        #pragma unroll
        for (int tt = 0; tt < TILE; tt++) {
            float p = pr[tt];
            tsum += p;
            kbar0 += p * cur[tt * II + tid];
            kbar1 += p * cur[tt * II + tid + 256];
        }
        l = l * scale + tsum;
        m_run = m_new;

        // issue tile t+2 (buffer last read two barriers ago -> safe)
        if (t + 2 < NTILES) {
            const float* src = keyb + (size_t)(t + 2) * TILE * II;
            float* nxt = bufs + ((t + 2) % NBUF) * TILE * II;
            #pragma unroll
            for (int j = 0; j < 4; j++) {
                int idx = tid + j * NTHREADS;
                cp_async16(nxt + idx * 4, src + idx * 4);
            }
            cp_async_commit();
        }
    }

    const int pidx = blockIdx.x;
    g_pkbar[(size_t)pidx * II + tid] = kbar0;
    g_pkbar[(size_t)pidx * II + tid + 256] = kbar1;
    if (tid == 0) { g_pm[pidx] = m_run; g_pl[pidx] = l; }

    // ---- last block of this batch: combine partials -> g_kbar ----
    __shared__ int lastflag;
    __shared__ float w_sh[NCH];
    __shared__ float invl_sh;
    __threadfence();
    __syncthreads();
    if (tid == 0) {
        int v = atomicAdd(&g_cnt[b], 1);
        lastflag = (v == NCH - 1);
    }
    __syncthreads();
    if (!lastflag) return;
    __threadfence();

    if (warp == 0) {
        float pm = (lane < NCH) ? g_pm[b * NCH + lane] : -3.0e38f;
        float pl = (lane < NCH) ? g_pl[b * NCH + lane] : 0.f;
        float M = pm;
        #pragma unroll
        for (int off = 16; off > 0; off >>= 1)
            M = fmaxf(M, __shfl_xor_sync(0xffffffffu, M, off));
        float w = __expf(pm - M);
        if (lane < NCH) w_sh[lane] = w;
        float lw = pl * w;
        #pragma unroll
        for (int off = 16; off > 0; off >>= 1)
            lw += __shfl_xor_sync(0xffffffffu, lw, off);
        if (lane == 0) invl_sh = 1.f / lw;
    }
    __syncthreads();

    float kb0 = 0.f, kb1 = 0.f;
    #pragma unroll
    for (int cc = 0; cc < NCH; cc++) {
        float w = w_sh[cc];
        kb0 += g_pkbar[(size_t)(b * NCH + cc) * II + tid] * w;
        kb1 += g_pkbar[(size_t)(b * NCH + cc) * II + tid + 256] * w;
    }
    float invl = invl_sh;
    g_kbar[b * II + tid] = kb0 * invl;
    g_kbar[b * II + tid + 256] = kb1 * invl;

    if (tid == 0) g_cnt[b] = 0;   // reset for graph replay
}

// ============================================================
// Kernel C: projection. Each Wk row read ONCE chip-wide.
// grid = HH/8 = 64 blocks; warp w owns h = blk*8+w.
// ============================================================
__global__ void __launch_bounds__(256) project(
    const float* __restrict__ Wk, const float* __restrict__ bk,
    float* __restrict__ out)
{
    const int tid = threadIdx.x;
    const int lane = tid & 31;
    const int warp = tid >> 5;
    const int h = blockIdx.x * 8 + warp;

    extern __shared__ float kb_sh[];   // BB*II floats = 64KB
    float4* kb4s = (float4*)kb_sh;
    const float4* gk4 = (const float4*)g_kbar;
    #pragma unroll
    for (int j = 0; j < 16; j++)
        kb4s[tid + j * 256] = gk4[tid + j * 256];
    __syncthreads();

    const float4* w4 = (const float4*)(Wk + (size_t)h * II);
    float4 wr[4];
    #pragma unroll
    for (int j = 0; j < 4; j++) wr[j] = w4[lane + j * 32];
    const float bkh = bk[h];

    #pragma unroll 4
    for (int b = 0; b < BB; b++) {
        const float4* kb4 = (const float4*)(kb_sh + b * II);
        float acc = 0.f;
        #pragma unroll
        for (int j = 0; j < 4; j++) {
            float4 c4 = kb4[lane + j * 32];
            acc += wr[j].x * c4.x + wr[j].y * c4.y + wr[j].z * c4.z + wr[j].w * c4.w;
        }
        #pragma unroll
        for (int off = 16; off > 0; off >>= 1)
            acc += __shfl_down_sync(0xffffffffu, acc, off);
        if (lane == 0) out[b * HH + h] = acc + bkh;
    }
}

// ============================================================
extern "C" void kernel_launch(void* const* d_in, const int* in_sizes, int n_in,
                              void* d_out, int out_size) {
    const float* query = (const float*)d_in[0];
    const float* key   = (const float*)d_in[1];
    const int*   mask  = (const int*)d_in[2];
    const float* Wq   = (const float*)d_in[3];
    const float* bq   = (const float*)d_in[4];
    const float* Wk   = (const float*)d_in[5];
    const float* bk   = (const float*)d_in[6];
    const float* Wout = (const float*)d_in[7];
    float* out = (float*)d_out;

    const size_t smem_main = (NBUF * TILE * II + TILE) * sizeof(float) + CHUNK * sizeof(int);
    const size_t smem_proj = BB * II * sizeof(float);
    cudaFuncSetAttribute(main_pass, cudaFuncAttributeMaxDynamicSharedMemorySize, (int)smem_main);
    cudaFuncSetAttribute(project, cudaFuncAttributeMaxDynamicSharedMemorySize, (int)smem_proj);

    prep_fused<<<256, 256>>>(query, Wk, Wq, bq, bk, Wout);
    main_pass<<<BB * NCH, NTHREADS, smem_main>>>(key, mask, out);
    project<<<HH / 8, 256, smem_proj>>>(Wk, bk, out);
}

// round 9
// speedup vs baseline: 1.1624x; 1.1624x over previous
#include <cuda_runtime.h>
#include <math.h>
#include <stdint.h>

#define BB 32
#define SS 4096
#define II 512
#define HH 512
#define NCH 16
#define CHUNK (SS / NCH)      // 256 positions per block
#define WPOS (CHUNK / 8)      // 32 positions per warp
#define NBUF 3
#define NTHREADS 256
#define NEG_INF_F (-1e18f)
#define HSPLIT 8

// -------- persistent device scratch (no allocations allowed) --------
__device__ float g_part[2 * HSPLIT * II];  // [mat][hs][i] partials
__device__ float g_w2[II];                 // Wk^T @ Wout
__device__ float g_qoff[BB];               // per-batch additive score offset
__device__ float g_pm[BB * NCH];           // partial max
__device__ float g_pl[BB * NCH];           // partial sumexp
__device__ float g_pkbar[BB * NCH * II];   // partial weighted key sums
__device__ float g_kbar[BB * II];          // combined softmax-weighted key mean

// -------- cp.async helpers --------
__device__ __forceinline__ void cp_async16(void* dst_smem, const void* src_gmem) {
    unsigned d = (unsigned)__cvta_generic_to_shared(dst_smem);
    asm volatile("cp.async.cg.shared.global [%0], [%1], 16;\n" :: "r"(d), "l"(src_gmem));
}
__device__ __forceinline__ void cp_async_commit() {
    asm volatile("cp.async.commit_group;\n");
}
__device__ __forceinline__ void cp_async_wait1() {
    asm volatile("cp.async.wait_group 1;\n");
}
__device__ __forceinline__ void cp_async_wait0() {
    asm volatile("cp.async.wait_group 0;\n");
}

// ============================================================
// Kernel A1: partial projected-weight vectors (round-7 verbatim).
// ============================================================
__global__ void __launch_bounds__(256) prep_partial(
    const float* __restrict__ Wk, const float* __restrict__ Wq,
    const float* __restrict__ Wout)
{
    const int blk = blockIdx.x;
    const int mat = blk >> 7;
    const int rem = blk & 127;
    const int hs  = rem >> 4;
    const int ig  = rem & 15;
    const int i0  = ig * 32;
    const int h0  = hs * 64;
    const int tid = threadIdx.x;
    const int il   = tid & 31;
    const int hsub = tid >> 5;

    const float* W = mat ? Wq : Wk;

    __shared__ float wout_sh[64];
    __shared__ float red[256];
    if (tid < 64) wout_sh[tid] = Wout[h0 + tid];
    __syncthreads();

    float acc = 0.f;
    #pragma unroll
    for (int k = 0; k < 8; k++) {
        int hl = hsub * 8 + k;
        acc += W[(size_t)(h0 + hl) * II + i0 + il] * wout_sh[hl];
    }
    red[tid] = acc;
    __syncthreads();
    if (tid < 128) red[tid] += red[tid + 128];
    __syncthreads();
    if (tid < 64) red[tid] += red[tid + 64];
    __syncthreads();
    if (tid < 32)
        g_part[(mat * HSPLIT + hs) * II + i0 + tid] = red[tid] + red[tid + 32];
}

// ============================================================
// Kernel A2: combine partials (round-7 verbatim).
// ============================================================
__global__ void __launch_bounds__(512) prep_combine(
    const float* __restrict__ query,
    const float* __restrict__ bq, const float* __restrict__ bk,
    const float* __restrict__ Wout)
{
    const int tid = threadIdx.x;
    if (blockIdx.x == 32) {
        float s = 0.f;
        #pragma unroll
        for (int hs = 0; hs < HSPLIT; hs++)
            s += g_part[hs * II + tid];
        g_w2[tid] = s;
        return;
    }
    const int b = blockIdx.x;
    __shared__ float wq2_sh[II];
    __shared__ float red[512];

    float s = 0.f;
    #pragma unroll
    for (int hs = 0; hs < HSPLIT; hs++)
        s += g_part[(HSPLIT + hs) * II + tid];
    wq2_sh[tid] = s;

    red[tid] = Wout[tid] * (bq[tid] + bk[tid]);
    __syncthreads();
    for (int off = 256; off > 0; off >>= 1) {
        if (tid < off) red[tid] += red[tid + off];
        __syncthreads();
    }
    float cbias = red[0];
    __syncthreads();

    red[tid] = query[(size_t)b * II + tid] * wq2_sh[tid];
    __syncthreads();
    for (int off = 256; off > 0; off >>= 1) {
        if (tid < off) red[tid] += red[tid + off];
        __syncthreads();
    }
    if (tid == 0) g_qoff[b] = red[0] + cbias;
}

// ============================================================
// Kernel B: warp-autonomous streaming pass. Each warp owns 32
// contiguous positions with its own triple-buffered cp.async
// pipeline and its own online softmax. NO block barriers in the
// main loop; one merge at the end.
// ============================================================
__global__ void __launch_bounds__(NTHREADS, 4) main_pass(
    const float* __restrict__ key,
    const int* __restrict__ mask,
    float* __restrict__ out)
{
    const int b = blockIdx.x / NCH;
    const int c = blockIdx.x % NCH;
    const int tid = threadIdx.x;
    const int lane = tid & 31;
    const int warp = tid >> 5;
    const int s0 = c * CHUNK;
    const int sw = s0 + warp * WPOS;      // this warp's first position

    extern __shared__ float smem[];
    float* bufs = smem;                       // 8 warps * NBUF * II floats (48KB)
    float* stage = smem;                      // reused after main loop (8*II floats)
    int* mask_sh = (int*)(smem + 8 * NBUF * II);  // CHUNK ints
    __shared__ float m_sh[8];
    __shared__ float l_sh[8];

    mask_sh[tid] = mask[(size_t)b * SS + s0 + tid];

    float* mybuf = bufs + warp * NBUF * II;
    const float* keyw = key + (size_t)b * SS * II + (size_t)sw * II;

    float w2r[16];
    #pragma unroll
    for (int k = 0; k < 16; k++) w2r[k] = g_w2[lane + 32 * k];

    const float qoff = g_qoff[b];

    float kbar[16];
    #pragma unroll
    for (int k = 0; k < 16; k++) kbar[k] = 0.f;
    float l = 0.f;
    float m_run = -3.0e38f;
    float myscore = 0.f;

    __syncwarp();  // mask_sh rows for this warp written by... own warp? No:
    __syncthreads(); // mask_sh[warp*32..] written by threads of other warps -> one barrier up front

    // prefetch rows 0 and 1 (each row: 128 float4, 4 per lane)
    #pragma unroll
    for (int pt = 0; pt < 2; pt++) {
        const float* src = keyw + (size_t)pt * II;
        float* dst = mybuf + pt * II;
        #pragma unroll
        for (int j = 0; j < 4; j++) {
            int idx = lane + j * 32;
            cp_async16(dst + idx * 4, src + idx * 4);
        }
        cp_async_commit();
    }

    #pragma unroll 1
    for (int p = 0; p < WPOS; p++) {
        float* cur = mybuf + (p % NBUF) * II;
        if (p + 1 < WPOS) cp_async_wait1();
        else cp_async_wait0();
        __syncwarp();

        // score: dot(row, w2) via lane-parallel + xor-reduce (all lanes get it)
        float acc = 0.f;
        #pragma unroll
        for (int k = 0; k < 16; k++)
            acc += cur[lane + 32 * k] * w2r[k];
        #pragma unroll
        for (int off = 16; off > 0; off >>= 1)
            acc += __shfl_xor_sync(0xffffffffu, acc, off);

        float sc = acc + qoff;
        if (mask_sh[warp * WPOS + p] != 0) sc = NEG_INF_F;
        if (lane == p) myscore = sc;   // lane p keeps score p

        float m_new = fmaxf(m_run, sc);
        float scale = __expf(m_run - m_new);
        float pcur  = __expf(sc - m_new);
        l = l * scale + pcur;
        #pragma unroll
        for (int k = 0; k < 16; k++)
            kbar[k] = kbar[k] * scale + pcur * cur[lane + 32 * k];
        m_run = m_new;

        // issue row p+2 (buffer last consumed at p-1; syncwarp above fences)
        if (p + 2 < WPOS) {
            const float* src = keyw + (size_t)(p + 2) * II;
            float* nxt = mybuf + ((p + 2) % NBUF) * II;
            #pragma unroll
            for (int j = 0; j < 4; j++) {
                int idx = lane + j * 32;
                cp_async16(nxt + idx * 4, src + idx * 4);
            }
            cp_async_commit();
        }
    }

    // coalesced attn_weight store: 128B per warp
    out[(size_t)BB * HH + (size_t)b * SS + sw + lane] = myscore;

    // ---- merge 8 warp-partials ----
    __syncthreads();   // buffers dead; reuse as staging
    #pragma unroll
    for (int k = 0; k < 16; k++)
        stage[warp * II + lane + 32 * k] = kbar[k];
    if (lane == 0) { m_sh[warp] = m_run; l_sh[warp] = l; }
    __syncthreads();

    // block-level combine (redundant per thread; 8 exps each, once)
    float M = -3.0e38f;
    #pragma unroll
    for (int w = 0; w < 8; w++) M = fmaxf(M, m_sh[w]);
    float wt[8];
    float lblk = 0.f;
    #pragma unroll
    for (int w = 0; w < 8; w++) {
        wt[w] = __expf(m_sh[w] - M);
        lblk += l_sh[w] * wt[w];
    }
    float kb0 = 0.f, kb1 = 0.f;
    #pragma unroll
    for (int w = 0; w < 8; w++) {
        kb0 += stage[w * II + tid] * wt[w];
        kb1 += stage[w * II + tid + 256] * wt[w];
    }

    const int pidx = blockIdx.x;
    g_pkbar[(size_t)pidx * II + tid] = kb0;
    g_pkbar[(size_t)pidx * II + tid + 256] = kb1;
    if (tid == 0) { g_pm[pidx] = M; g_pl[pidx] = lblk; }
}

// ============================================================
// Kernel C1: combine chunk partials -> g_kbar (round-7 verbatim).
// ============================================================
__global__ void __launch_bounds__(128) combine_kbar(void)
{
    const int b   = blockIdx.x >> 2;
    const int i0  = (blockIdx.x & 3) * 128;
    const int tid = threadIdx.x;
    const int lane = tid & 31;
    const int warp = tid >> 5;

    __shared__ float w_sh[NCH];
    __shared__ float invl_sh;

    if (warp == 0) {
        float pm = (lane < NCH) ? g_pm[b * NCH + lane] : -3.0e38f;
        float pl = (lane < NCH) ? g_pl[b * NCH + lane] : 0.f;
        float M = pm;
        #pragma unroll
        for (int off = 16; off > 0; off >>= 1)
            M = fmaxf(M, __shfl_xor_sync(0xffffffffu, M, off));
        float w = __expf(pm - M);
        if (lane < NCH) w_sh[lane] = w;
        float lw = pl * w;
        #pragma unroll
        for (int off = 16; off > 0; off >>= 1)
            lw += __shfl_xor_sync(0xffffffffu, lw, off);
        if (lane == 0) invl_sh = 1.f / lw;
    }
    __syncthreads();

    const int i = i0 + tid;
    float kb = 0.f;
    #pragma unroll
    for (int c = 0; c < NCH; c++)
        kb += g_pkbar[(size_t)(b * NCH + c) * II + i] * w_sh[c];
    g_kbar[b * II + i] = kb * invl_sh;
}

// ============================================================
// Kernel C2: projection (round-7 verbatim).
// ============================================================
__global__ void __launch_bounds__(256) project(
    const float* __restrict__ Wk, const float* __restrict__ bk,
    float* __restrict__ out)
{
    const int tid = threadIdx.x;
    const int lane = tid & 31;
    const int warp = tid >> 5;
    const int h = blockIdx.x * 8 + warp;

    extern __shared__ float kb_sh[];   // BB*II floats = 64KB
    float4* kb4s = (float4*)kb_sh;
    const float4* gk4 = (const float4*)g_kbar;
    #pragma unroll
    for (int j = 0; j < 16; j++)
        kb4s[tid + j * 256] = gk4[tid + j * 256];
    __syncthreads();

    const float4* w4 = (const float4*)(Wk + (size_t)h * II);
    float4 wr[4];
    #pragma unroll
    for (int j = 0; j < 4; j++) wr[j] = w4[lane + j * 32];
    const float bkh = bk[h];

    #pragma unroll 4
    for (int b = 0; b < BB; b++) {
        const float4* kb4 = (const float4*)(kb_sh + b * II);
        float acc = 0.f;
        #pragma unroll
        for (int j = 0; j < 4; j++) {
            float4 c4 = kb4[lane + j * 32];
            acc += wr[j].x * c4.x + wr[j].y * c4.y + wr[j].z * c4.z + wr[j].w * c4.w;
        }
        #pragma unroll
        for (int off = 16; off > 0; off >>= 1)
            acc += __shfl_down_sync(0xffffffffu, acc, off);
        if (lane == 0) out[b * HH + h] = acc + bkh;
    }
}

// ============================================================
extern "C" void kernel_launch(void* const* d_in, const int* in_sizes, int n_in,
                              void* d_out, int out_size) {
    const float* query = (const float*)d_in[0];
    const float* key   = (const float*)d_in[1];
    const int*   mask  = (const int*)d_in[2];
    const float* Wq   = (const float*)d_in[3];
    const float* bq   = (const float*)d_in[4];
    const float* Wk   = (const float*)d_in[5];
    const float* bk   = (const float*)d_in[6];
    const float* Wout = (const float*)d_in[7];
    float* out = (float*)d_out;

    const size_t smem_main = (8 * NBUF * II) * sizeof(float) + CHUNK * sizeof(int);
    const size_t smem_proj = BB * II * sizeof(float);
    cudaFuncSetAttribute(main_pass, cudaFuncAttributeMaxDynamicSharedMemorySize, (int)smem_main);
    cudaFuncSetAttribute(project, cudaFuncAttributeMaxDynamicSharedMemorySize, (int)smem_proj);

    prep_partial<<<256, 256>>>(Wk, Wq, Wout);
    prep_combine<<<33, 512>>>(query, bq, bk, Wout);
    main_pass<<<BB * NCH, NTHREADS, smem_main>>>(key, mask, out);
    combine_kbar<<<BB * 4, 128>>>();
    project<<<HH / 8, 256, smem_proj>>>(Wk, bk, out);
}

// round 10
// speedup vs baseline: 1.3973x; 1.2021x over previous
#include <cuda_runtime.h>
#include <math.h>
#include <stdint.h>

#define BB 32
#define SS 4096
#define II 512
#define HH 512
#define NCH 8
#define CHUNK (SS / NCH)      // 512 positions per block
#define WPOS (CHUNK / 8)      // 64 positions per warp
#define NTHREADS 256
#define NEG_INF_F (-1e18f)
#define HSPLIT 8

// -------- persistent device scratch (no allocations allowed) --------
__device__ float g_part[2 * HSPLIT * II];  // [mat][hs][i] partials
__device__ float g_w2[II];                 // Wk^T @ Wout
__device__ float g_qoff[BB];               // per-batch additive score offset
__device__ float g_kacc[BB * II];          // atomic accumulator: sum exp(s)*key
__device__ float g_lacc[BB];               // atomic accumulator: sum exp(s)

// ============================================================
// Kernel A1: partial projected-weight vectors + zero accumulators.
// ============================================================
__global__ void __launch_bounds__(256) prep_partial(
    const float* __restrict__ Wk, const float* __restrict__ Wq,
    const float* __restrict__ Wout)
{
    const int blk = blockIdx.x;
    const int tid = threadIdx.x;

    // zero the atomic accumulators for this graph replay
    if (blk < 64) g_kacc[blk * 256 + tid] = 0.f;
    if (blk == 64 && tid < BB) g_lacc[tid] = 0.f;

    const int mat = blk >> 7;
    const int rem = blk & 127;
    const int hs  = rem >> 4;
    const int ig  = rem & 15;
    const int i0  = ig * 32;
    const int h0  = hs * 64;
    const int il   = tid & 31;
    const int hsub = tid >> 5;

    const float* W = mat ? Wq : Wk;

    __shared__ float wout_sh[64];
    __shared__ float red[256];
    if (tid < 64) wout_sh[tid] = Wout[h0 + tid];
    __syncthreads();

    float acc = 0.f;
    #pragma unroll
    for (int k = 0; k < 8; k++) {
        int hl = hsub * 8 + k;
        acc += W[(size_t)(h0 + hl) * II + i0 + il] * wout_sh[hl];
    }
    red[tid] = acc;
    __syncthreads();
    if (tid < 128) red[tid] += red[tid + 128];
    __syncthreads();
    if (tid < 64) red[tid] += red[tid + 64];
    __syncthreads();
    if (tid < 32)
        g_part[(mat * HSPLIT + hs) * II + i0 + tid] = red[tid] + red[tid + 32];
}

// ============================================================
// Kernel A2: combine partials -> g_w2, g_qoff (unchanged).
// ============================================================
__global__ void __launch_bounds__(512) prep_combine(
    const float* __restrict__ query,
    const float* __restrict__ bq, const float* __restrict__ bk,
    const float* __restrict__ Wout)
{
    const int tid = threadIdx.x;
    if (blockIdx.x == 32) {
        float s = 0.f;
        #pragma unroll
        for (int hs = 0; hs < HSPLIT; hs++)
            s += g_part[hs * II + tid];
        g_w2[tid] = s;
        return;
    }
    const int b = blockIdx.x;
    __shared__ float wq2_sh[II];
    __shared__ float red[512];

    float s = 0.f;
    #pragma unroll
    for (int hs = 0; hs < HSPLIT; hs++)
        s += g_part[(HSPLIT + hs) * II + tid];
    wq2_sh[tid] = s;

    red[tid] = Wout[tid] * (bq[tid] + bk[tid]);
    __syncthreads();
    for (int off = 256; off > 0; off >>= 1) {
        if (tid < off) red[tid] += red[tid + off];
        __syncthreads();
    }
    float cbias = red[0];
    __syncthreads();

    red[tid] = query[(size_t)b * II + tid] * wq2_sh[tid];
    __syncthreads();
    for (int off = 256; off > 0; off >>= 1) {
        if (tid < off) red[tid] += red[tid + off];
        __syncthreads();
    }
    if (tid == 0) g_qoff[b] = red[0] + cbias;
}

// ============================================================
// Kernel B: pure-register streaming pass. No smem/cp.async in
// the loop. Max-free softmax (exp of raw dot; bounded). Block
// merges warp partials in smem once, then atomicAdd to g_kacc.
// ============================================================
__global__ void __launch_bounds__(NTHREADS, 2) main_pass(
    const float* __restrict__ key,
    const int* __restrict__ mask,
    float* __restrict__ out)
{
    const int b = blockIdx.x / NCH;
    const int c = blockIdx.x % NCH;
    const int tid = threadIdx.x;
    const int lane = tid & 31;
    const int warp = tid >> 5;
    const int s0 = c * CHUNK;
    const int sw = s0 + warp * WPOS;

    const float4* keyw = (const float4*)(key + (size_t)b * SS * II + (size_t)sw * II);

    // mask for this warp's 64 positions: 2 ints per lane
    const int m0 = mask[(size_t)b * SS + sw + lane];
    const int m1 = mask[(size_t)b * SS + sw + 32 + lane];

    // w2 slice: elements 4*lane + 128*j (+0..3)
    const float4* w24 = (const float4*)g_w2;
    float4 w2r[4];
    #pragma unroll
    for (int j = 0; j < 4; j++) w2r[j] = w24[lane + 32 * j];

    const float qoff = g_qoff[b];

    float4 kb[4];
    #pragma unroll
    for (int j = 0; j < 4; j++) kb[j] = make_float4(0.f, 0.f, 0.f, 0.f);
    float l = 0.f;
    float sc0 = NEG_INF_F, sc1 = NEG_INF_F;  // lane L keeps scores L and L+32

    // 4-deep rotating register pipeline
    float4 KV[4][4];
    #pragma unroll
    for (int r = 0; r < 4; r++) {
        #pragma unroll
        for (int j = 0; j < 4; j++)
            KV[r][j] = keyw[(size_t)r * 128 + lane + 32 * j];
    }

    #pragma unroll 1
    for (int p = 0; p < WPOS; p += 4) {
        #pragma unroll
        for (int q = 0; q < 4; q++) {
            const int pp = p + q;
            // score dot
            float acc = KV[q][0].x * w2r[0].x + KV[q][0].y * w2r[0].y
                      + KV[q][0].z * w2r[0].z + KV[q][0].w * w2r[0].w;
            #pragma unroll
            for (int j = 1; j < 4; j++)
                acc += KV[q][j].x * w2r[j].x + KV[q][j].y * w2r[j].y
                     + KV[q][j].z * w2r[j].z + KV[q][j].w * w2r[j].w;
            #pragma unroll
            for (int off = 16; off > 0; off >>= 1)
                acc += __shfl_xor_sync(0xffffffffu, acc, off);

            const int mv = __shfl_sync(0xffffffffu, (pp & 32) ? m1 : m0, pp & 31);
            const float e = mv ? 0.f : __expf(acc);
            const float scst = mv ? NEG_INF_F : acc + qoff;
            if (lane == (pp & 31)) {
                if (pp < 32) sc0 = scst; else sc1 = scst;
            }
            l += e;
            #pragma unroll
            for (int j = 0; j < 4; j++) {
                kb[j].x += e * KV[q][j].x;
                kb[j].y += e * KV[q][j].y;
                kb[j].z += e * KV[q][j].z;
                kb[j].w += e * KV[q][j].w;
            }
            // prefetch row pp+4 into the set just consumed
            if (pp + 4 < WPOS) {
                #pragma unroll
                for (int j = 0; j < 4; j++)
                    KV[q][j] = keyw[(size_t)(pp + 4) * 128 + lane + 32 * j];
            }
        }
    }

    // attn_weight: two coalesced 128B stores per warp
    out[(size_t)BB * HH + (size_t)b * SS + sw + lane] = sc0;
    out[(size_t)BB * HH + (size_t)b * SS + sw + 32 + lane] = sc1;

    // ---- block merge (plain sums; all partials share scale) ----
    __shared__ float stage[8 * II];   // 16KB
    __shared__ float l_sh[8];
    float4* st4 = (float4*)(stage + warp * II);
    #pragma unroll
    for (int j = 0; j < 4; j++) st4[lane + 32 * j] = kb[j];
    if (lane == 0) l_sh[warp] = l;   // l identical across lanes
    __syncthreads();

    float t0 = 0.f, t1 = 0.f;
    #pragma unroll
    for (int w = 0; w < 8; w++) {
        t0 += stage[w * II + tid];
        t1 += stage[w * II + tid + 256];
    }
    atomicAdd(&g_kacc[b * II + tid], t0);
    atomicAdd(&g_kacc[b * II + tid + 256], t1);
    if (tid == 0) {
        float lt = 0.f;
        #pragma unroll
        for (int w = 0; w < 8; w++) lt += l_sh[w];
        atomicAdd(&g_lacc[b], lt);
    }
}

// ============================================================
// Kernel C: projection. Normalizes while staging kbar; each Wk
// row read once chip-wide. grid = 64, warp w owns h = blk*8+w.
// ============================================================
__global__ void __launch_bounds__(256) project(
    const float* __restrict__ Wk, const float* __restrict__ bk,
    float* __restrict__ out)
{
    const int tid = threadIdx.x;
    const int lane = tid & 31;
    const int warp = tid >> 5;
    const int h = blockIdx.x * 8 + warp;

    extern __shared__ float kb_sh[];   // BB*II floats = 64KB
    __shared__ float linv_sh[BB];
    if (tid < BB) linv_sh[tid] = 1.f / g_lacc[tid];
    __syncthreads();

    float4* kb4s = (float4*)kb_sh;
    const float4* gk4 = (const float4*)g_kacc;
    #pragma unroll
    for (int j = 0; j < 16; j++) {
        int f = tid + j * 256;           // float4 index; 128 per batch
        float4 v = gk4[f];
        float li = linv_sh[f >> 7];
        v.x *= li; v.y *= li; v.z *= li; v.w *= li;
        kb4s[f] = v;
    }
    __syncthreads();

    const float4* w4 = (const float4*)(Wk + (size_t)h * II);
    float4 wr[4];
    #pragma unroll
    for (int j = 0; j < 4; j++) wr[j] = w4[lane + j * 32];
    const float bkh = bk[h];

    #pragma unroll 4
    for (int b = 0; b < BB; b++) {
        const float4* kb4 = (const float4*)(kb_sh + b * II);
        float acc = 0.f;
        #pragma unroll
        for (int j = 0; j < 4; j++) {
            float4 c4 = kb4[lane + j * 32];
            acc += wr[j].x * c4.x + wr[j].y * c4.y + wr[j].z * c4.z + wr[j].w * c4.w;
        }
        #pragma unroll
        for (int off = 16; off > 0; off >>= 1)
            acc += __shfl_down_sync(0xffffffffu, acc, off);
        if (lane == 0) out[b * HH + h] = acc + bkh;
    }
}

// ============================================================
extern "C" void kernel_launch(void* const* d_in, const int* in_sizes, int n_in,
                              void* d_out, int out_size) {
    const float* query = (const float*)d_in[0];
    const float* key   = (const float*)d_in[1];
    const int*   mask  = (const int*)d_in[2];
    const float* Wq   = (const float*)d_in[3];
    const float* bq   = (const float*)d_in[4];
    const float* Wk   = (const float*)d_in[5];
    const float* bk   = (const float*)d_in[6];
    const float* Wout = (const float*)d_in[7];
    float* out = (float*)d_out;

    const size_t smem_proj = BB * II * sizeof(float);
    cudaFuncSetAttribute(project, cudaFuncAttributeMaxDynamicSharedMemorySize, (int)smem_proj);

    prep_partial<<<256, 256>>>(Wk, Wq, Wout);
    prep_combine<<<33, 512>>>(query, bq, bk, Wout);
    main_pass<<<BB * NCH, NTHREADS>>>(key, mask, out);
    project<<<HH / 8, 256, smem_proj>>>(Wk, bk, out);
}

// round 11
// speedup vs baseline: 1.4650x; 1.0485x over previous
#include <cuda_runtime.h>
#include <math.h>
#include <stdint.h>

#define BB 32
#define SS 4096
#define II 512
#define HH 512
#define NCH 8
#define CHUNK (SS / NCH)      // 512 positions per block
#define WPOS (CHUNK / 8)      // 64 positions per warp
#define NTHREADS 256
#define NEG_INF_F (-1e18f)
#define HSPLIT 8
#define PGRP 8                // batches per project block

// -------- persistent device scratch (no allocations allowed) --------
__device__ float g_part[2 * HSPLIT * II];  // [mat][hs][i] partials
__device__ float g_w2[II];                 // Wk^T @ Wout
__device__ float g_qoff[BB];               // per-batch additive score offset
__device__ float g_kacc[BB * II];          // atomic accumulator: sum exp(s)*key
__device__ float g_lacc[BB];               // atomic accumulator: sum exp(s)

// ============================================================
// Kernel A1: partial projected-weight vectors + zero accumulators.
// ============================================================
__global__ void __launch_bounds__(256) prep_partial(
    const float* __restrict__ Wk, const float* __restrict__ Wq,
    const float* __restrict__ Wout)
{
    const int blk = blockIdx.x;
    const int tid = threadIdx.x;

    // zero the atomic accumulators for this graph replay
    if (blk < 64) g_kacc[blk * 256 + tid] = 0.f;
    if (blk == 64 && tid < BB) g_lacc[tid] = 0.f;

    const int mat = blk >> 7;
    const int rem = blk & 127;
    const int hs  = rem >> 4;
    const int ig  = rem & 15;
    const int i0  = ig * 32;
    const int h0  = hs * 64;
    const int il   = tid & 31;
    const int hsub = tid >> 5;

    const float* W = mat ? Wq : Wk;

    __shared__ float wout_sh[64];
    __shared__ float red[256];
    if (tid < 64) wout_sh[tid] = Wout[h0 + tid];
    __syncthreads();

    float acc = 0.f;
    #pragma unroll
    for (int k = 0; k < 8; k++) {
        int hl = hsub * 8 + k;
        acc += W[(size_t)(h0 + hl) * II + i0 + il] * wout_sh[hl];
    }
    red[tid] = acc;
    __syncthreads();
    if (tid < 128) red[tid] += red[tid + 128];
    __syncthreads();
    if (tid < 64) red[tid] += red[tid + 64];
    __syncthreads();
    if (tid < 32)
        g_part[(mat * HSPLIT + hs) * II + i0 + tid] = red[tid] + red[tid + 32];
}

// ============================================================
// Kernel A2: combine partials -> g_w2, g_qoff (unchanged).
// ============================================================
__global__ void __launch_bounds__(512) prep_combine(
    const float* __restrict__ query,
    const float* __restrict__ bq, const float* __restrict__ bk,
    const float* __restrict__ Wout)
{
    const int tid = threadIdx.x;
    if (blockIdx.x == 32) {
        float s = 0.f;
        #pragma unroll
        for (int hs = 0; hs < HSPLIT; hs++)
            s += g_part[hs * II + tid];
        g_w2[tid] = s;
        return;
    }
    const int b = blockIdx.x;
    __shared__ float wq2_sh[II];
    __shared__ float red[512];

    float s = 0.f;
    #pragma unroll
    for (int hs = 0; hs < HSPLIT; hs++)
        s += g_part[(HSPLIT + hs) * II + tid];
    wq2_sh[tid] = s;

    red[tid] = Wout[tid] * (bq[tid] + bk[tid]);
    __syncthreads();
    for (int off = 256; off > 0; off >>= 1) {
        if (tid < off) red[tid] += red[tid + off];
        __syncthreads();
    }
    float cbias = red[0];
    __syncthreads();

    red[tid] = query[(size_t)b * II + tid] * wq2_sh[tid];
    __syncthreads();
    for (int off = 256; off > 0; off >>= 1) {
        if (tid < off) red[tid] += red[tid + off];
        __syncthreads();
    }
    if (tid == 0) g_qoff[b] = red[0] + cbias;
}

// ============================================================
// Kernel B: pure-register streaming pass (unchanged from R10).
// ============================================================
__global__ void __launch_bounds__(NTHREADS, 2) main_pass(
    const float* __restrict__ key,
    const int* __restrict__ mask,
    float* __restrict__ out)
{
    const int b = blockIdx.x / NCH;
    const int c = blockIdx.x % NCH;
    const int tid = threadIdx.x;
    const int lane = tid & 31;
    const int warp = tid >> 5;
    const int s0 = c * CHUNK;
    const int sw = s0 + warp * WPOS;

    const float4* keyw = (const float4*)(key + (size_t)b * SS * II + (size_t)sw * II);

    const int m0 = mask[(size_t)b * SS + sw + lane];
    const int m1 = mask[(size_t)b * SS + sw + 32 + lane];

    const float4* w24 = (const float4*)g_w2;
    float4 w2r[4];
    #pragma unroll
    for (int j = 0; j < 4; j++) w2r[j] = w24[lane + 32 * j];

    const float qoff = g_qoff[b];

    float4 kb[4];
    #pragma unroll
    for (int j = 0; j < 4; j++) kb[j] = make_float4(0.f, 0.f, 0.f, 0.f);
    float l = 0.f;
    float sc0 = NEG_INF_F, sc1 = NEG_INF_F;

    float4 KV[4][4];
    #pragma unroll
    for (int r = 0; r < 4; r++) {
        #pragma unroll
        for (int j = 0; j < 4; j++)
            KV[r][j] = keyw[(size_t)r * 128 + lane + 32 * j];
    }

    #pragma unroll 1
    for (int p = 0; p < WPOS; p += 4) {
        #pragma unroll
        for (int q = 0; q < 4; q++) {
            const int pp = p + q;
            float acc = KV[q][0].x * w2r[0].x + KV[q][0].y * w2r[0].y
                      + KV[q][0].z * w2r[0].z + KV[q][0].w * w2r[0].w;
            #pragma unroll
            for (int j = 1; j < 4; j++)
                acc += KV[q][j].x * w2r[j].x + KV[q][j].y * w2r[j].y
                     + KV[q][j].z * w2r[j].z + KV[q][j].w * w2r[j].w;
            #pragma unroll
            for (int off = 16; off > 0; off >>= 1)
                acc += __shfl_xor_sync(0xffffffffu, acc, off);

            const int mv = __shfl_sync(0xffffffffu, (pp & 32) ? m1 : m0, pp & 31);
            const float e = mv ? 0.f : __expf(acc);
            const float scst = mv ? NEG_INF_F : acc + qoff;
            if (lane == (pp & 31)) {
                if (pp < 32) sc0 = scst; else sc1 = scst;
            }
            l += e;
            #pragma unroll
            for (int j = 0; j < 4; j++) {
                kb[j].x += e * KV[q][j].x;
                kb[j].y += e * KV[q][j].y;
                kb[j].z += e * KV[q][j].z;
                kb[j].w += e * KV[q][j].w;
            }
            if (pp + 4 < WPOS) {
                #pragma unroll
                for (int j = 0; j < 4; j++)
                    KV[q][j] = keyw[(size_t)(pp + 4) * 128 + lane + 32 * j];
            }
        }
    }

    out[(size_t)BB * HH + (size_t)b * SS + sw + lane] = sc0;
    out[(size_t)BB * HH + (size_t)b * SS + sw + 32 + lane] = sc1;

    __shared__ float stage[8 * II];
    __shared__ float l_sh[8];
    float4* st4 = (float4*)(stage + warp * II);
    #pragma unroll
    for (int j = 0; j < 4; j++) st4[lane + 32 * j] = kb[j];
    if (lane == 0) l_sh[warp] = l;
    __syncthreads();

    float t0 = 0.f, t1 = 0.f;
    #pragma unroll
    for (int w = 0; w < 8; w++) {
        t0 += stage[w * II + tid];
        t1 += stage[w * II + tid + 256];
    }
    atomicAdd(&g_kacc[b * II + tid], t0);
    atomicAdd(&g_kacc[b * II + tid + 256], t1);
    if (tid == 0) {
        float lt = 0.f;
        #pragma unroll
        for (int w = 0; w < 8; w++) lt += l_sh[w];
        atomicAdd(&g_lacc[b], lt);
    }
}

// ============================================================
// Kernel C: projection, split over 4 batch-groups.
// grid = 4 * 64 = 256 blocks; group g owns batches [g*8, g*8+8),
// h-block hb owns h = hb*8 + warp. Stages 16KB of kbar.
// ============================================================
__global__ void __launch_bounds__(256) project(
    const float* __restrict__ Wk, const float* __restrict__ bk,
    float* __restrict__ out)
{
    const int tid = threadIdx.x;
    const int lane = tid & 31;
    const int warp = tid >> 5;
    const int grp = blockIdx.x >> 6;          // 0..3
    const int hb  = blockIdx.x & 63;          // 0..63
    const int h = hb * 8 + warp;
    const int b0 = grp * PGRP;

    __shared__ float kb_sh[PGRP * II];        // 16KB
    __shared__ float linv_sh[PGRP];
    if (tid < PGRP) linv_sh[tid] = 1.f / g_lacc[b0 + tid];
    __syncthreads();

    // stage 8 batches' kbar, normalized: 1024 float4 / 256 threads = 4 each
    float4* kb4s = (float4*)kb_sh;
    const float4* gk4 = (const float4*)(g_kacc + (size_t)b0 * II);
    #pragma unroll
    for (int j = 0; j < 4; j++) {
        int f = tid + j * 256;                // float4 index; 128 per batch
        float4 v = gk4[f];
        float li = linv_sh[f >> 7];
        v.x *= li; v.y *= li; v.z *= li; v.w *= li;
        kb4s[f] = v;
    }
    __syncthreads();

    const float4* w4 = (const float4*)(Wk + (size_t)h * II);
    float4 wr[4];
    #pragma unroll
    for (int j = 0; j < 4; j++) wr[j] = w4[lane + j * 32];
    const float bkh = bk[h];

    #pragma unroll
    for (int bb = 0; bb < PGRP; bb++) {
        const float4* kb4 = (const float4*)(kb_sh + bb * II);
        float acc = 0.f;
        #pragma unroll
        for (int j = 0; j < 4; j++) {
            float4 c4 = kb4[lane + j * 32];
            acc += wr[j].x * c4.x + wr[j].y * c4.y + wr[j].z * c4.z + wr[j].w * c4.w;
        }
        #pragma unroll
        for (int off = 16; off > 0; off >>= 1)
            acc += __shfl_down_sync(0xffffffffu, acc, off);
        if (lane == 0) out[(b0 + bb) * HH + h] = acc + bkh;
    }
}

// ============================================================
extern "C" void kernel_launch(void* const* d_in, const int* in_sizes, int n_in,
                              void* d_out, int out_size) {
    const float* query = (const float*)d_in[0];
    const float* key   = (const float*)d_in[1];
    const int*   mask  = (const int*)d_in[2];
    const float* Wq   = (const float*)d_in[3];
    const float* bq   = (const float*)d_in[4];
    const float* Wk   = (const float*)d_in[5];
    const float* bk   = (const float*)d_in[6];
    const float* Wout = (const float*)d_in[7];
    float* out = (float*)d_out;

    prep_partial<<<256, 256>>>(Wk, Wq, Wout);
    prep_combine<<<33, 512>>>(query, bq, bk, Wout);
    main_pass<<<BB * NCH, NTHREADS>>>(key, mask, out);
    project<<<4 * (HH / 8), 256>>>(Wk, bk, out);
}